// round 2
// baseline (speedup 1.0000x reference)
#include <cuda_runtime.h>

// Problem constants
#define BHN 64          // B*H
#define TT 1024         // sequence length
#define DD 128          // head dim
static __device__ __constant__ float INV_TEMP = 0.08838834764831845f;  // 1/sqrt(128)

// ---------------------------------------------------------------------------
// Scratch: K-major (d-major) transposed copies of q_time (pre-scaled) and k_time
// ---------------------------------------------------------------------------
__device__ float g_qtT[(size_t)BHN * DD * TT];  // [bh][d][t], scaled by 1/TEMP
__device__ float g_ktT[(size_t)BHN * DD * TT];  // [bh][d][t]

// ---------------------------------------------------------------------------
// f32x2 packed helpers (sm_103a FFMA2)
// ---------------------------------------------------------------------------
typedef unsigned long long u64t;

__device__ __forceinline__ u64t pk2(float lo, float hi) {
    u64t r; asm("mov.b64 %0, {%1, %2};" : "=l"(r) : "f"(lo), "f"(hi)); return r;
}
__device__ __forceinline__ void fma2(u64t& d, u64t a, u64t b) {
    asm("fma.rn.f32x2 %0, %1, %2, %0;" : "+l"(d) : "l"(a), "l"(b));
}
__device__ __forceinline__ void up2(u64t v, float& a, float& b) {
    asm("mov.b64 {%0, %1}, %2;" : "=f"(a), "=f"(b) : "l"(v));
}

// ---------------------------------------------------------------------------
// Kernel 0: transpose q_time (scaled) and k_time into [bh][d][t] scratch
// grid (T/32, BH, 2), block 256
// ---------------------------------------------------------------------------
__global__ void transpose_qk_kernel(const float* __restrict__ qt,
                                    const float* __restrict__ kt) {
    __shared__ float tile[32][33];
    const int t0 = blockIdx.x * 32;
    const int bh = blockIdx.y;
    const bool isq = (blockIdx.z == 0);
    const float* src = (isq ? qt : kt) + (size_t)bh * TT * DD;
    float* dst = (isq ? g_qtT : g_ktT) + (size_t)bh * DD * TT;
    const float scale = isq ? INV_TEMP : 1.0f;
    const int tid = threadIdx.x;

    for (int d0 = 0; d0 < DD; d0 += 32) {
        #pragma unroll
        for (int i = 0; i < 4; i++) {
            int idx = i * 256 + tid;
            int r = idx >> 5, c = idx & 31;          // r = t-local, c = d-local
            tile[r][c] = src[(size_t)(t0 + r) * DD + d0 + c] * scale;
        }
        __syncthreads();
        #pragma unroll
        for (int i = 0; i < 4; i++) {
            int idx = i * 256 + tid;
            int r = idx >> 5, c = idx & 31;          // r = d-local, c = t-local
            dst[(size_t)(d0 + r) * TT + t0 + c] = tile[c][r];
        }
        __syncthreads();
    }
}

// ---------------------------------------------------------------------------
// Kernel 1: feature attention.  scores_f[d,e] = sum_t qf[t,d]*kf[t,e]/TEMP,
// softmax over e, write attn_feature [bh][d][e].
// grid (4, BH): block computes 32 d-rows x 128 e-cols, K = 1024 over t.
// block 256 threads (16x16), thread tile 2x8.
// ---------------------------------------------------------------------------
__global__ void __launch_bounds__(256) feature_attn_kernel(
    const float* __restrict__ qf, const float* __restrict__ kf,
    float* __restrict__ attn_f) {
    __shared__ float qs[32 * 34];    // [t][d-slice(32)] pad->34
    __shared__ float ks[32 * 132];   // [t][e(128)] pad->132
    __shared__ float Sf[32 * 132];   // [d-slice][e]

    const int bh = blockIdx.y;
    const int d0blk = blockIdx.x * 32;
    const float* q = qf + (size_t)bh * TT * DD;
    const float* k = kf + (size_t)bh * TT * DD;
    const int tid = threadIdx.x;
    const int ty = tid >> 4, tx = tid & 15;
    const int r0 = ty * 2;           // local d-row pair
    const int e0 = tx * 8;           // e columns

    u64t acc[2][4];
    #pragma unroll
    for (int i = 0; i < 2; i++)
        #pragma unroll
        for (int j = 0; j < 4; j++) acc[i][j] = 0ull;

    for (int tt = 0; tt < TT; tt += 32) {
        // load q slice 32x32 (scaled here by INV_TEMP)
        #pragma unroll
        for (int i = 0; i < 4; i++) {
            int idx = i * 256 + tid;
            int r = idx >> 5, c = idx & 31;
            qs[r * 34 + c] = q[(size_t)(tt + r) * DD + d0blk + c] * INV_TEMP;
        }
        // load k tile 32x128 as float4
        #pragma unroll
        for (int i = 0; i < 4; i++) {
            int idx = i * 256 + tid;
            int r = idx >> 5, c4 = (idx & 31) * 4;
            *(float4*)&ks[r * 132 + c4] = *(const float4*)&k[(size_t)(tt + r) * DD + c4];
        }
        __syncthreads();
        #pragma unroll 4
        for (int t = 0; t < 32; t++) {
            float2 a = *(float2*)&qs[t * 34 + r0];
            ulonglong2 b0 = *(ulonglong2*)&ks[t * 132 + e0];
            ulonglong2 b1 = *(ulonglong2*)&ks[t * 132 + e0 + 4];
            u64t a0 = pk2(a.x, a.x), a1 = pk2(a.y, a.y);
            fma2(acc[0][0], a0, b0.x); fma2(acc[0][1], a0, b0.y);
            fma2(acc[0][2], a0, b1.x); fma2(acc[0][3], a0, b1.y);
            fma2(acc[1][0], a1, b0.x); fma2(acc[1][1], a1, b0.y);
            fma2(acc[1][2], a1, b1.x); fma2(acc[1][3], a1, b1.y);
        }
        __syncthreads();
    }

    // write scores to Sf
    #pragma unroll
    for (int i = 0; i < 2; i++) {
        float x[8];
        up2(acc[i][0], x[0], x[1]); up2(acc[i][1], x[2], x[3]);
        up2(acc[i][2], x[4], x[5]); up2(acc[i][3], x[6], x[7]);
        *(float4*)&Sf[(r0 + i) * 132 + e0]     = make_float4(x[0], x[1], x[2], x[3]);
        *(float4*)&Sf[(r0 + i) * 132 + e0 + 4] = make_float4(x[4], x[5], x[6], x[7]);
    }
    __syncthreads();

    // softmax rows: warp w handles rows 4w..4w+3
    const int lane = tid & 31, w = tid >> 5;
    float* af = attn_f + (size_t)bh * DD * DD;
    #pragma unroll
    for (int rr = 0; rr < 4; rr++) {
        int r = w * 4 + rr;
        float vv[4], mx = -1e30f;
        #pragma unroll
        for (int kk = 0; kk < 4; kk++) {
            vv[kk] = Sf[r * 132 + lane + 32 * kk];
            mx = fmaxf(mx, vv[kk]);
        }
        #pragma unroll
        for (int o = 16; o; o >>= 1) mx = fmaxf(mx, __shfl_xor_sync(~0u, mx, o));
        float ssum = 0.f;
        #pragma unroll
        for (int kk = 0; kk < 4; kk++) { vv[kk] = __expf(vv[kk] - mx); ssum += vv[kk]; }
        #pragma unroll
        for (int o = 16; o; o >>= 1) ssum += __shfl_xor_sync(~0u, ssum, o);
        float iv = 1.0f / ssum;
        #pragma unroll
        for (int kk = 0; kk < 4; kk++)
            af[(size_t)(d0blk + r) * DD + lane + 32 * kk] = vv[kk] * iv;
    }
}

// ---------------------------------------------------------------------------
// Kernel 2: fused time attention + tv + output.
// grid (T/32, BH), block 256. One 32-row tile of one (b,h).
// Phases:  GEMM1 scores -> ST[s][r] (s-major), exp+rowsum, normalize + write
//          attn_time, GEMM2 tv = A@v, GEMM3 out = tv@attn_feature.
// ---------------------------------------------------------------------------
#define ST_STR 34
#define QT_STR 36
#define KT_STR 68
#define VS_STR 132
// smem layout (floats):
//   ST  : 1024*34 = 34816    (scores [s][r]; later reused for F[128][132])
//   qTs : 128*36  = 4608     (qT tile [d][r]; later reused for tvT[d][r])
//   kvs : 8704               (kT tile [128][68] or v tile [64][132])
//   inv : 32
#define SMEM_FLOATS (34816 + 4608 + 8704 + 32)
#define SMEM_BYTES  (SMEM_FLOATS * 4)

__global__ void __launch_bounds__(256, 1) time_attn_kernel(
    const float* __restrict__ v_in, const float* __restrict__ attn_f_g,
    float* __restrict__ out, float* __restrict__ attn_t_g) {
    extern __shared__ float sm[];
    float* ST  = sm;
    float* qTs = sm + 34816;
    float* kvs = qTs + 4608;
    float* inv = kvs + 8704;

    const int bh = blockIdx.y;
    const int t0 = blockIdx.x * 32;
    const int tid = threadIdx.x;
    const int ty = tid >> 4, tx = tid & 15;
    const int lane = tid & 31, w = tid >> 5;

    const float* qT = g_qtT + (size_t)bh * DD * TT;   // [d][t] (prescaled)
    const float* kT = g_ktT + (size_t)bh * DD * TT;   // [d][t]
    const float* vv = v_in + (size_t)bh * TT * DD;    // [s][d]

    // load qTs[d][r] = qT[d][t0+r] : 128x32 floats, 16 per thread
    #pragma unroll
    for (int i = 0; i < 4; i++) {
        int l = i * 256 + tid;
        int dd = l >> 3, c4 = (l & 7) * 4;
        *(float4*)&qTs[dd * QT_STR + c4] = *(const float4*)&qT[(size_t)dd * TT + t0 + c4];
    }

    // ---------------- GEMM1: ST[c][r] = sum_d qTs[d][r] * kT[d][c] ---------
    {
        const int r0 = ty * 2, c0 = tx * 4;
        for (int j = 0; j < 16; j++) {
            __syncthreads();   // kvs reuse guard (also covers initial qTs fill)
            #pragma unroll
            for (int i = 0; i < 8; i++) {
                int l = i * 256 + tid;
                int dd = l >> 4, c4 = (l & 15) * 4;
                *(float4*)&kvs[dd * KT_STR + c4] =
                    *(const float4*)&kT[(size_t)dd * TT + j * 64 + c4];
            }
            __syncthreads();
            u64t acc[2][2] = {{0ull, 0ull}, {0ull, 0ull}};
            #pragma unroll 4
            for (int d = 0; d < 128; d++) {
                float2 a = *(float2*)&qTs[d * QT_STR + r0];
                ulonglong2 b = *(ulonglong2*)&kvs[d * KT_STR + c0];
                u64t a0 = pk2(a.x, a.x), a1 = pk2(a.y, a.y);
                fma2(acc[0][0], a0, b.x); fma2(acc[0][1], a0, b.y);
                fma2(acc[1][0], a1, b.x); fma2(acc[1][1], a1, b.y);
            }
            #pragma unroll
            for (int i = 0; i < 2; i++) {
                float x0, x1, x2, x3;
                up2(acc[i][0], x0, x1); up2(acc[i][1], x2, x3);
                int cb = (j * 64 + c0) * ST_STR + r0 + i;
                ST[cb]              = x0;
                ST[cb + ST_STR]     = x1;
                ST[cb + 2 * ST_STR] = x2;
                ST[cb + 3 * ST_STR] = x3;
            }
        }
    }
    __syncthreads();

    // ---------------- softmax (unstable exp is safe: |score| <~ 7) --------
    #pragma unroll
    for (int rr = 0; rr < 4; rr++) {
        int r = w * 4 + rr;
        float ssum = 0.f;
        #pragma unroll 4
        for (int s = lane; s < TT; s += 32) {
            float e = __expf(ST[s * ST_STR + r]);
            ST[s * ST_STR + r] = e;
            ssum += e;
        }
        #pragma unroll
        for (int o = 16; o; o >>= 1) ssum += __shfl_xor_sync(~0u, ssum, o);
        if (lane == 0) inv[r] = 1.0f / ssum;
    }
    __syncthreads();

    // normalize in place + coalesced write of attn_time
    {
        float* at = attn_t_g + ((size_t)bh * TT + t0) * TT;
        #pragma unroll
        for (int rr = 0; rr < 4; rr++) {
            int r = w * 4 + rr;
            float iv = inv[r];
            #pragma unroll 4
            for (int s = lane; s < TT; s += 32) {
                float val = ST[s * ST_STR + r] * iv;
                ST[s * ST_STR + r] = val;
                at[(size_t)r * TT + s] = val;
            }
        }
    }
    __syncthreads();

    // ---------------- GEMM2: tv[r][d] = sum_s A[r][s] * v[s][d] -----------
    u64t acc2[2][4];
    #pragma unroll
    for (int i = 0; i < 2; i++)
        #pragma unroll
        for (int j = 0; j < 4; j++) acc2[i][j] = 0ull;
    {
        const int r0 = ty * 2, d0 = tx * 8;
        for (int j = 0; j < 16; j++) {
            __syncthreads();   // kvs reuse guard
            #pragma unroll
            for (int i = 0; i < 8; i++) {
                int l = i * 256 + tid;
                int ss = l >> 5, c4 = (l & 31) * 4;
                *(float4*)&kvs[ss * VS_STR + c4] =
                    *(const float4*)&vv[(size_t)(j * 64 + ss) * DD + c4];
            }
            __syncthreads();
            #pragma unroll 2
            for (int s = 0; s < 64; s++) {
                float2 a = *(float2*)&ST[(j * 64 + s) * ST_STR + r0];
                ulonglong2 b0 = *(ulonglong2*)&kvs[s * VS_STR + d0];
                ulonglong2 b1 = *(ulonglong2*)&kvs[s * VS_STR + d0 + 4];
                u64t a0 = pk2(a.x, a.x), a1 = pk2(a.y, a.y);
                fma2(acc2[0][0], a0, b0.x); fma2(acc2[0][1], a0, b0.y);
                fma2(acc2[0][2], a0, b1.x); fma2(acc2[0][3], a0, b1.y);
                fma2(acc2[1][0], a1, b0.x); fma2(acc2[1][1], a1, b0.y);
                fma2(acc2[1][2], a1, b1.x); fma2(acc2[1][3], a1, b1.y);
            }
        }
    }

    // store tvT[d][r] into qTs region (no one reads qTs anymore; per-thread cells)
    {
        const int r0 = ty * 2, d0 = tx * 8;
        #pragma unroll
        for (int i = 0; i < 2; i++) {
            float x[8];
            up2(acc2[i][0], x[0], x[1]); up2(acc2[i][1], x[2], x[3]);
            up2(acc2[i][2], x[4], x[5]); up2(acc2[i][3], x[6], x[7]);
            #pragma unroll
            for (int jj = 0; jj < 8; jj++)
                qTs[(d0 + jj) * QT_STR + r0 + i] = x[jj];
        }
    }
    __syncthreads();   // all ST reads (GEMM2) done; now reuse ST for F

    // load attn_feature F[d][e] into ST region, stride 132
    float* FS = ST;
    {
        const float* af = attn_f_g + (size_t)bh * DD * DD;
        #pragma unroll
        for (int i = 0; i < 16; i++) {
            int l = i * 256 + tid;
            int dd = l >> 5, c4 = (l & 31) * 4;
            *(float4*)&FS[dd * 132 + c4] = *(const float4*)&af[(size_t)dd * DD + c4];
        }
    }
    __syncthreads();

    // ---------------- GEMM3: out[r][e] = sum_d tvT[d][r] * F[d][e] --------
    {
        const int r0 = ty * 2, e0 = tx * 8;
        u64t acc3[2][4];
        #pragma unroll
        for (int i = 0; i < 2; i++)
            #pragma unroll
            for (int j = 0; j < 4; j++) acc3[i][j] = 0ull;
        #pragma unroll 4
        for (int d = 0; d < 128; d++) {
            float2 a = *(float2*)&qTs[d * QT_STR + r0];   // tvT
            ulonglong2 b0 = *(ulonglong2*)&FS[d * 132 + e0];
            ulonglong2 b1 = *(ulonglong2*)&FS[d * 132 + e0 + 4];
            u64t a0 = pk2(a.x, a.x), a1 = pk2(a.y, a.y);
            fma2(acc3[0][0], a0, b0.x); fma2(acc3[0][1], a0, b0.y);
            fma2(acc3[0][2], a0, b1.x); fma2(acc3[0][3], a0, b1.y);
            fma2(acc3[1][0], a1, b0.x); fma2(acc3[1][1], a1, b0.y);
            fma2(acc3[1][2], a1, b1.x); fma2(acc3[1][3], a1, b1.y);
        }
        float* op = out + ((size_t)bh * TT + t0) * DD;
        #pragma unroll
        for (int i = 0; i < 2; i++) {
            float x[8];
            up2(acc3[i][0], x[0], x[1]); up2(acc3[i][1], x[2], x[3]);
            up2(acc3[i][2], x[4], x[5]); up2(acc3[i][3], x[6], x[7]);
            *(float4*)&op[(size_t)(r0 + i) * DD + e0]     = make_float4(x[0], x[1], x[2], x[3]);
            *(float4*)&op[(size_t)(r0 + i) * DD + e0 + 4] = make_float4(x[4], x[5], x[6], x[7]);
        }
    }
}

// ---------------------------------------------------------------------------
// Launch
// ---------------------------------------------------------------------------
extern "C" void kernel_launch(void* const* d_in, const int* in_sizes, int n_in,
                              void* d_out, int out_size) {
    const float* q_time    = (const float*)d_in[0];
    const float* k_time    = (const float*)d_in[1];
    const float* q_feature = (const float*)d_in[2];
    const float* k_feature = (const float*)d_in[3];
    const float* v         = (const float*)d_in[4];

    float* out    = (float*)d_out;                       // [BH][T][D]
    float* attn_t = out + (size_t)BHN * TT * DD;         // [BH][T][T]
    float* attn_f = attn_t + (size_t)BHN * TT * TT;      // [BH][D][D]

    cudaFuncSetAttribute(time_attn_kernel,
                         cudaFuncAttributeMaxDynamicSharedMemorySize, SMEM_BYTES);

    transpose_qk_kernel<<<dim3(TT / 32, BHN, 2), 256>>>(q_time, k_time);
    feature_attn_kernel<<<dim3(4, BHN), 256>>>(q_feature, k_feature, attn_f);
    time_attn_kernel<<<dim3(TT / 32, BHN), 256, SMEM_BYTES>>>(v, attn_f, out, attn_t);
}

// round 3
// speedup vs baseline: 1.9661x; 1.9661x over previous
#include <cuda_runtime.h>

// Problem constants
#define BHN 64          // B*H
#define TT 1024         // sequence length
#define DD 128          // head dim
#define TILE 128
#define KC 16
static __device__ __constant__ float INV_TEMP = 0.08838834764831845f;  // 1/sqrt(128)

// ---------------------------------------------------------------------------
// Scratch: K-major (d-major) transposed copies of q_time (pre-scaled) and k_time
// ---------------------------------------------------------------------------
__device__ float g_qtT[(size_t)BHN * DD * TT];  // [bh][d][t], scaled by 1/TEMP
__device__ float g_ktT[(size_t)BHN * DD * TT];  // [bh][d][t]

// ---------------------------------------------------------------------------
// f32x2 packed helpers (sm_103a FFMA2)
// ---------------------------------------------------------------------------
typedef unsigned long long u64t;

__device__ __forceinline__ u64t pk2(float lo, float hi) {
    u64t r; asm("mov.b64 %0, {%1, %2};" : "=l"(r) : "f"(lo), "f"(hi)); return r;
}
__device__ __forceinline__ void fma2(u64t& d, u64t a, u64t b) {
    asm("fma.rn.f32x2 %0, %1, %2, %0;" : "+l"(d) : "l"(a), "l"(b));
}
__device__ __forceinline__ void up2(u64t v, float& a, float& b) {
    asm("mov.b64 {%0, %1}, %2;" : "=f"(a), "=f"(b) : "l"(v));
}

// ---------------------------------------------------------------------------
// Kernel 0: transpose q_time (scaled) and k_time into [bh][d][t] scratch
// ---------------------------------------------------------------------------
__global__ void transpose_qk_kernel(const float* __restrict__ qt,
                                    const float* __restrict__ kt) {
    __shared__ float tile[32][33];
    const int t0 = blockIdx.x * 32;
    const int bh = blockIdx.y;
    const bool isq = (blockIdx.z == 0);
    const float* src = (isq ? qt : kt) + (size_t)bh * TT * DD;
    float* dst = (isq ? g_qtT : g_ktT) + (size_t)bh * DD * TT;
    const float scale = isq ? INV_TEMP : 1.0f;
    const int tid = threadIdx.x;

    for (int d0 = 0; d0 < DD; d0 += 32) {
        #pragma unroll
        for (int i = 0; i < 4; i++) {
            int idx = i * 256 + tid;
            int r = idx >> 5, c = idx & 31;
            tile[r][c] = src[(size_t)(t0 + r) * DD + d0 + c] * scale;
        }
        __syncthreads();
        #pragma unroll
        for (int i = 0; i < 4; i++) {
            int idx = i * 256 + tid;
            int r = idx >> 5, c = idx & 31;
            dst[(size_t)(d0 + r) * TT + t0 + c] = tile[c][r];
        }
        __syncthreads();
    }
}

// ---------------------------------------------------------------------------
// Kernel 1: feature attention (unchanged; ~80us, not the bottleneck)
// ---------------------------------------------------------------------------
__global__ void __launch_bounds__(256) feature_attn_kernel(
    const float* __restrict__ qf, const float* __restrict__ kf,
    float* __restrict__ attn_f) {
    __shared__ float qs[32 * 34];
    __shared__ float ks[32 * 132];
    __shared__ float Sf[32 * 132];

    const int bh = blockIdx.y;
    const int d0blk = blockIdx.x * 32;
    const float* q = qf + (size_t)bh * TT * DD;
    const float* k = kf + (size_t)bh * TT * DD;
    const int tid = threadIdx.x;
    const int ty = tid >> 4, tx = tid & 15;
    const int r0 = ty * 2;
    const int e0 = tx * 8;

    u64t acc[2][4];
    #pragma unroll
    for (int i = 0; i < 2; i++)
        #pragma unroll
        for (int j = 0; j < 4; j++) acc[i][j] = 0ull;

    for (int tt = 0; tt < TT; tt += 32) {
        #pragma unroll
        for (int i = 0; i < 4; i++) {
            int idx = i * 256 + tid;
            int r = idx >> 5, c = idx & 31;
            qs[r * 34 + c] = q[(size_t)(tt + r) * DD + d0blk + c] * INV_TEMP;
        }
        #pragma unroll
        for (int i = 0; i < 4; i++) {
            int idx = i * 256 + tid;
            int r = idx >> 5, c4 = (idx & 31) * 4;
            *(float4*)&ks[r * 132 + c4] = *(const float4*)&k[(size_t)(tt + r) * DD + c4];
        }
        __syncthreads();
        #pragma unroll 4
        for (int t = 0; t < 32; t++) {
            float2 a = *(float2*)&qs[t * 34 + r0];
            ulonglong2 b0 = *(ulonglong2*)&ks[t * 132 + e0];
            ulonglong2 b1 = *(ulonglong2*)&ks[t * 132 + e0 + 4];
            u64t a0 = pk2(a.x, a.x), a1 = pk2(a.y, a.y);
            fma2(acc[0][0], a0, b0.x); fma2(acc[0][1], a0, b0.y);
            fma2(acc[0][2], a0, b1.x); fma2(acc[0][3], a0, b1.y);
            fma2(acc[1][0], a1, b0.x); fma2(acc[1][1], a1, b0.y);
            fma2(acc[1][2], a1, b1.x); fma2(acc[1][3], a1, b1.y);
        }
        __syncthreads();
    }

    #pragma unroll
    for (int i = 0; i < 2; i++) {
        float x[8];
        up2(acc[i][0], x[0], x[1]); up2(acc[i][1], x[2], x[3]);
        up2(acc[i][2], x[4], x[5]); up2(acc[i][3], x[6], x[7]);
        *(float4*)&Sf[(r0 + i) * 132 + e0]     = make_float4(x[0], x[1], x[2], x[3]);
        *(float4*)&Sf[(r0 + i) * 132 + e0 + 4] = make_float4(x[4], x[5], x[6], x[7]);
    }
    __syncthreads();

    const int lane = tid & 31, w = tid >> 5;
    float* af = attn_f + (size_t)bh * DD * DD;
    #pragma unroll
    for (int rr = 0; rr < 4; rr++) {
        int r = w * 4 + rr;
        float vv[4], mx = -1e30f;
        #pragma unroll
        for (int kk = 0; kk < 4; kk++) {
            vv[kk] = Sf[r * 132 + lane + 32 * kk];
            mx = fmaxf(mx, vv[kk]);
        }
        #pragma unroll
        for (int o = 16; o; o >>= 1) mx = fmaxf(mx, __shfl_xor_sync(~0u, mx, o));
        float ssum = 0.f;
        #pragma unroll
        for (int kk = 0; kk < 4; kk++) { vv[kk] = __expf(vv[kk] - mx); ssum += vv[kk]; }
        #pragma unroll
        for (int o = 16; o; o >>= 1) ssum += __shfl_xor_sync(~0u, ssum, o);
        float iv = 1.0f / ssum;
        #pragma unroll
        for (int kk = 0; kk < 4; kk++)
            af[(size_t)(d0blk + r) * DD + lane + 32 * kk] = vv[kk] * iv;
    }
}

// ---------------------------------------------------------------------------
// Kernel T1: scores + exp + rowsum + in-kernel normalize.
// grid (8, 64), block 256, 8x8 thread tiles, 128x128 block tile per col step.
// Writes normalized attn_time.
// ---------------------------------------------------------------------------
__global__ void __launch_bounds__(256, 2) score_kernel(float* __restrict__ attn_t) {
    __shared__ float As[2][KC * TILE];   // qT chunk [k][r]
    __shared__ float Bs[2][KC * TILE];   // kT chunk [k][c]
    __shared__ float red[TILE * 17];
    __shared__ float invs[TILE];

    const int bh = blockIdx.y;
    const int r0 = blockIdx.x * TILE;
    const int tid = threadIdx.x;
    const int ty = tid >> 4, tx = tid & 15;

    const float* qT = g_qtT + (size_t)bh * DD * TT;
    const float* kT = g_ktT + (size_t)bh * DD * TT;
    float* E = attn_t + ((size_t)bh * TT + r0) * TT;

    const int lr0 = tid >> 5;            // 0..7
    const int lc0 = (tid & 31) * 4;
    const int lr1 = lr0 + 8;

    float rsum[8] = {0, 0, 0, 0, 0, 0, 0, 0};

    for (int c0 = 0; c0 < TT; c0 += TILE) {
        u64t acc[32];
        #pragma unroll
        for (int i = 0; i < 32; i++) acc[i] = 0ull;

        // prologue: chunk 0
        float4 ra0 = *(const float4*)&qT[(size_t)lr0 * TT + r0 + lc0];
        float4 ra1 = *(const float4*)&qT[(size_t)lr1 * TT + r0 + lc0];
        float4 rb0 = *(const float4*)&kT[(size_t)lr0 * TT + c0 + lc0];
        float4 rb1 = *(const float4*)&kT[(size_t)lr1 * TT + c0 + lc0];
        __syncthreads();   // previous col-tile fully done with buffers
        *(float4*)&As[0][lr0 * TILE + lc0] = ra0;
        *(float4*)&As[0][lr1 * TILE + lc0] = ra1;
        *(float4*)&Bs[0][lr0 * TILE + lc0] = rb0;
        *(float4*)&Bs[0][lr1 * TILE + lc0] = rb1;
        __syncthreads();

        for (int kc = 0; kc < DD / KC; kc++) {
            const int cur = kc & 1;
            if (kc < DD / KC - 1) {
                const float* qp = qT + (size_t)(kc + 1) * KC * TT;
                const float* kp = kT + (size_t)(kc + 1) * KC * TT;
                ra0 = *(const float4*)&qp[(size_t)lr0 * TT + r0 + lc0];
                ra1 = *(const float4*)&qp[(size_t)lr1 * TT + r0 + lc0];
                rb0 = *(const float4*)&kp[(size_t)lr0 * TT + c0 + lc0];
                rb1 = *(const float4*)&kp[(size_t)lr1 * TT + c0 + lc0];
            }
            #pragma unroll
            for (int k = 0; k < KC; k++) {
                const float* ap = &As[cur][k * TILE + ty * 8];
                const float* bp = &Bs[cur][k * TILE + tx * 8];
                float4 aA = *(const float4*)ap;
                float4 aB = *(const float4*)(ap + 4);
                ulonglong2 bA = *(const ulonglong2*)bp;
                ulonglong2 bB = *(const ulonglong2*)(bp + 4);
                float av[8] = {aA.x, aA.y, aA.z, aA.w, aB.x, aB.y, aB.z, aB.w};
                #pragma unroll
                for (int i = 0; i < 8; i++) {
                    u64t ai = pk2(av[i], av[i]);
                    fma2(acc[i * 4 + 0], ai, bA.x);
                    fma2(acc[i * 4 + 1], ai, bA.y);
                    fma2(acc[i * 4 + 2], ai, bB.x);
                    fma2(acc[i * 4 + 3], ai, bB.y);
                }
            }
            if (kc < DD / KC - 1) {
                const int nxt = cur ^ 1;
                __syncthreads();
                *(float4*)&As[nxt][lr0 * TILE + lc0] = ra0;
                *(float4*)&As[nxt][lr1 * TILE + lc0] = ra1;
                *(float4*)&Bs[nxt][lr0 * TILE + lc0] = rb0;
                *(float4*)&Bs[nxt][lr1 * TILE + lc0] = rb1;
                __syncthreads();
            }
        }

        // epilogue: exp + rowsum + store unnormalized E
        float* Ec = E + c0;
        #pragma unroll
        for (int i = 0; i < 8; i++) {
            float x[8];
            up2(acc[i * 4 + 0], x[0], x[1]); up2(acc[i * 4 + 1], x[2], x[3]);
            up2(acc[i * 4 + 2], x[4], x[5]); up2(acc[i * 4 + 3], x[6], x[7]);
            float s = 0.f;
            #pragma unroll
            for (int j = 0; j < 8; j++) { x[j] = __expf(x[j]); s += x[j]; }
            rsum[i] += s;
            *(float4*)&Ec[(size_t)(ty * 8 + i) * TT + tx * 8]     = make_float4(x[0], x[1], x[2], x[3]);
            *(float4*)&Ec[(size_t)(ty * 8 + i) * TT + tx * 8 + 4] = make_float4(x[4], x[5], x[6], x[7]);
        }
    }

    // rowsum reduction across tx
    #pragma unroll
    for (int i = 0; i < 8; i++) red[(ty * 8 + i) * 17 + tx] = rsum[i];
    __syncthreads();
    if (tid < TILE) {
        float s = 0.f;
        #pragma unroll
        for (int j = 0; j < 16; j++) s += red[tid * 17 + j];
        invs[tid] = 1.0f / s;
    }
    __syncthreads();

    // normalize pass: re-read this CTA's 512KB (L2-hot), scale, rewrite
    float4* E4 = (float4*)E;
    #pragma unroll 4
    for (int i = 0; i < TILE; i++) {
        float iv = invs[i];
        float4 vv = E4[(size_t)i * (TT / 4) + tid];
        vv.x *= iv; vv.y *= iv; vv.z *= iv; vv.w *= iv;
        E4[(size_t)i * (TT / 4) + tid] = vv;
    }
}

// ---------------------------------------------------------------------------
// Kernel T2: tv = attn_time @ V (K=1024 streamed), then out = tv @ attn_feature.
// grid (8, 64), block 256, 8x8 thread tiles.
// Dynamic smem: As[2][16*136] | Bs[2][16*128] | Ts[128*136]; Fs aliases As.
// ---------------------------------------------------------------------------
#define AS_STR 136
#define T2_AS_FLOATS (2 * KC * AS_STR)          // 4352
#define T2_BS_FLOATS (2 * KC * TILE)            // 4096
#define T2_TS_FLOATS (TILE * AS_STR)            // 17408
#define T2_SMEM_FLOATS (T2_AS_FLOATS + T2_BS_FLOATS + T2_TS_FLOATS)
#define T2_SMEM_BYTES (T2_SMEM_FLOATS * 4)

__global__ void __launch_bounds__(256, 2) tv_out_kernel(
    const float* __restrict__ attn_t, const float* __restrict__ v_in,
    const float* __restrict__ attn_f, float* __restrict__ out) {
    extern __shared__ float sm[];
    float* Asb = sm;                          // staged A^T chunks [s][r], stride AS_STR
    float* Bsb = sm + T2_AS_FLOATS;           // V chunks [s][d], stride TILE
    float* Ts  = Bsb + T2_BS_FLOATS;          // tv^T [d][r], stride AS_STR
    float* Fs  = Asb;                         // GEMM3 F chunk [k][e], stride 132

    const int bh = blockIdx.y;
    const int r0 = blockIdx.x * TILE;
    const int tid = threadIdx.x;
    const int ty = tid >> 4, tx = tid & 15;

    const float* A = attn_t + ((size_t)bh * TT + r0) * TT;
    const float* V = v_in + (size_t)bh * TT * DD;
    const float* F = attn_f + (size_t)bh * DD * DD;

    // A staging: thread loads A[arow][sc*16 + ac .. +7], stores transposed
    const int arow = tid >> 1;
    const int ac = (tid & 1) * 8;
    // B staging: direct copy indices
    const int lr0 = tid >> 5, lc0 = (tid & 31) * 4, lr1 = lr0 + 8;

    u64t acc[32];
    #pragma unroll
    for (int i = 0; i < 32; i++) acc[i] = 0ull;

    // prologue: chunk 0
    float4 ra0 = *(const float4*)&A[(size_t)arow * TT + ac];
    float4 ra1 = *(const float4*)&A[(size_t)arow * TT + ac + 4];
    float4 rb0 = *(const float4*)&V[(size_t)lr0 * DD + lc0];
    float4 rb1 = *(const float4*)&V[(size_t)lr1 * DD + lc0];
    {
        float* Ad = Asb;  // buf 0
        Ad[(ac + 0) * AS_STR + arow] = ra0.x;
        Ad[(ac + 1) * AS_STR + arow] = ra0.y;
        Ad[(ac + 2) * AS_STR + arow] = ra0.z;
        Ad[(ac + 3) * AS_STR + arow] = ra0.w;
        Ad[(ac + 4) * AS_STR + arow] = ra1.x;
        Ad[(ac + 5) * AS_STR + arow] = ra1.y;
        Ad[(ac + 6) * AS_STR + arow] = ra1.z;
        Ad[(ac + 7) * AS_STR + arow] = ra1.w;
        *(float4*)&Bsb[lr0 * TILE + lc0] = rb0;
        *(float4*)&Bsb[lr1 * TILE + lc0] = rb1;
    }
    __syncthreads();

    for (int sc = 0; sc < TT / KC; sc++) {
        const int cur = sc & 1;
        if (sc < TT / KC - 1) {
            const int s1 = (sc + 1) * KC;
            ra0 = *(const float4*)&A[(size_t)arow * TT + s1 + ac];
            ra1 = *(const float4*)&A[(size_t)arow * TT + s1 + ac + 4];
            rb0 = *(const float4*)&V[(size_t)(s1 + lr0) * DD + lc0];
            rb1 = *(const float4*)&V[(size_t)(s1 + lr1) * DD + lc0];
        }
        const float* Ac = Asb + cur * (KC * AS_STR);
        const float* Bc = Bsb + cur * (KC * TILE);
        #pragma unroll
        for (int k = 0; k < KC; k++) {
            const float* ap = &Ac[k * AS_STR + ty * 8];
            const float* bp = &Bc[k * TILE + tx * 8];
            float4 aA = *(const float4*)ap;
            float4 aB = *(const float4*)(ap + 4);
            ulonglong2 bA = *(const ulonglong2*)bp;
            ulonglong2 bB = *(const ulonglong2*)(bp + 4);
            float av[8] = {aA.x, aA.y, aA.z, aA.w, aB.x, aB.y, aB.z, aB.w};
            #pragma unroll
            for (int i = 0; i < 8; i++) {
                u64t ai = pk2(av[i], av[i]);
                fma2(acc[i * 4 + 0], ai, bA.x);
                fma2(acc[i * 4 + 1], ai, bA.y);
                fma2(acc[i * 4 + 2], ai, bB.x);
                fma2(acc[i * 4 + 3], ai, bB.y);
            }
        }
        if (sc < TT / KC - 1) {
            const int nxt = cur ^ 1;
            __syncthreads();
            float* Ad = Asb + nxt * (KC * AS_STR);
            Ad[(ac + 0) * AS_STR + arow] = ra0.x;
            Ad[(ac + 1) * AS_STR + arow] = ra0.y;
            Ad[(ac + 2) * AS_STR + arow] = ra0.z;
            Ad[(ac + 3) * AS_STR + arow] = ra0.w;
            Ad[(ac + 4) * AS_STR + arow] = ra1.x;
            Ad[(ac + 5) * AS_STR + arow] = ra1.y;
            Ad[(ac + 6) * AS_STR + arow] = ra1.z;
            Ad[(ac + 7) * AS_STR + arow] = ra1.w;
            float* Bd = Bsb + nxt * (KC * TILE);
            *(float4*)&Bd[lr0 * TILE + lc0] = rb0;
            *(float4*)&Bd[lr1 * TILE + lc0] = rb1;
            __syncthreads();
        }
    }

    // store tv^T[d][r]: per output-col j (a d value), 8 row values are contiguous r
    #pragma unroll
    for (int j2 = 0; j2 < 4; j2++) {
        float lo[8], hi[8];
        #pragma unroll
        for (int i = 0; i < 8; i++) up2(acc[i * 4 + j2], lo[i], hi[i]);
        int d_lo = tx * 8 + j2 * 2, d_hi = d_lo + 1;
        *(float4*)&Ts[d_lo * AS_STR + ty * 8]     = make_float4(lo[0], lo[1], lo[2], lo[3]);
        *(float4*)&Ts[d_lo * AS_STR + ty * 8 + 4] = make_float4(lo[4], lo[5], lo[6], lo[7]);
        *(float4*)&Ts[d_hi * AS_STR + ty * 8]     = make_float4(hi[0], hi[1], hi[2], hi[3]);
        *(float4*)&Ts[d_hi * AS_STR + ty * 8 + 4] = make_float4(hi[4], hi[5], hi[6], hi[7]);
    }

    // GEMM3: out = tv @ F, k = d in chunks of 16 (Fs aliases As buffers)
    #pragma unroll
    for (int i = 0; i < 32; i++) acc[i] = 0ull;
    for (int dc = 0; dc < DD / KC; dc++) {
        __syncthreads();
        *(float4*)&Fs[lr0 * 132 + lc0] = *(const float4*)&F[(size_t)(dc * KC + lr0) * DD + lc0];
        *(float4*)&Fs[lr1 * 132 + lc0] = *(const float4*)&F[(size_t)(dc * KC + lr1) * DD + lc0];
        __syncthreads();
        #pragma unroll
        for (int k = 0; k < KC; k++) {
            const float* ap = &Ts[(dc * KC + k) * AS_STR + ty * 8];
            const float* bp = &Fs[k * 132 + tx * 8];
            float4 aA = *(const float4*)ap;
            float4 aB = *(const float4*)(ap + 4);
            ulonglong2 bA = *(const ulonglong2*)bp;
            ulonglong2 bB = *(const ulonglong2*)(bp + 4);
            float av[8] = {aA.x, aA.y, aA.z, aA.w, aB.x, aB.y, aB.z, aB.w};
            #pragma unroll
            for (int i = 0; i < 8; i++) {
                u64t ai = pk2(av[i], av[i]);
                fma2(acc[i * 4 + 0], ai, bA.x);
                fma2(acc[i * 4 + 1], ai, bA.y);
                fma2(acc[i * 4 + 2], ai, bB.x);
                fma2(acc[i * 4 + 3], ai, bB.y);
            }
        }
    }

    float* op = out + ((size_t)bh * TT + r0) * DD;
    #pragma unroll
    for (int i = 0; i < 8; i++) {
        float x[8];
        up2(acc[i * 4 + 0], x[0], x[1]); up2(acc[i * 4 + 1], x[2], x[3]);
        up2(acc[i * 4 + 2], x[4], x[5]); up2(acc[i * 4 + 3], x[6], x[7]);
        *(float4*)&op[(size_t)(ty * 8 + i) * DD + tx * 8]     = make_float4(x[0], x[1], x[2], x[3]);
        *(float4*)&op[(size_t)(ty * 8 + i) * DD + tx * 8 + 4] = make_float4(x[4], x[5], x[6], x[7]);
    }
}

// ---------------------------------------------------------------------------
// Launch
// ---------------------------------------------------------------------------
extern "C" void kernel_launch(void* const* d_in, const int* in_sizes, int n_in,
                              void* d_out, int out_size) {
    const float* q_time    = (const float*)d_in[0];
    const float* k_time    = (const float*)d_in[1];
    const float* q_feature = (const float*)d_in[2];
    const float* k_feature = (const float*)d_in[3];
    const float* v         = (const float*)d_in[4];

    float* out    = (float*)d_out;                       // [BH][T][D]
    float* attn_t = out + (size_t)BHN * TT * DD;         // [BH][T][T]
    float* attn_f = attn_t + (size_t)BHN * TT * TT;      // [BH][D][D]

    cudaFuncSetAttribute(tv_out_kernel,
                         cudaFuncAttributeMaxDynamicSharedMemorySize, T2_SMEM_BYTES);

    transpose_qk_kernel<<<dim3(TT / 32, BHN, 2), 256>>>(q_time, k_time);
    feature_attn_kernel<<<dim3(4, BHN), 256>>>(q_feature, k_feature, attn_f);
    score_kernel<<<dim3(TT / TILE, BHN), 256>>>(attn_t);
    tv_out_kernel<<<dim3(TT / TILE, BHN), 256, T2_SMEM_BYTES>>>(attn_t, v, attn_f, out);
}

// round 5
// speedup vs baseline: 2.9386x; 1.4946x over previous
#include <cuda_runtime.h>
#include <cuda_bf16.h>
#include <cstdint>

// Problem constants
#define BHN 64          // B*H
#define TT 1024         // sequence length
#define DD 128          // head dim
static __device__ __constant__ float INV_TEMP = 0.08838834764831845f;  // 1/sqrt(128)

// Scratch
__device__ float g_vT[(size_t)BHN * DD * TT];   // [bh][d][t]  (V transposed: B col-major for tv GEMM)
__device__ float g_ft[(size_t)BHN * DD * DD];   // [bh][e][d]  (attn_feature transposed: B col-major for out GEMM)

typedef unsigned long long u64t;

// ---------------------------------------------------------------------------
// helpers
// ---------------------------------------------------------------------------
__device__ __forceinline__ uint32_t smem_u32(const void* p) {
    uint32_t a;
    asm("{ .reg .u64 t; cvta.to.shared.u64 t, %1; cvt.u32.u64 %0, t; }" : "=r"(a) : "l"(p));
    return a;
}
// pack two f32 to bf16x2: low half = first arg
__device__ __forceinline__ uint32_t pack_bf2(float lo, float hi) {
    uint32_t r;
    asm("cvt.rn.bf16x2.f32 %0, %1, %2;" : "=r"(r) : "f"(hi), "f"(lo));
    return r;
}
__device__ __forceinline__ void ldsm4(uint32_t addr, uint32_t r[4]) {
    asm volatile("ldmatrix.sync.aligned.m8n8.x4.shared.b16 {%0,%1,%2,%3}, [%4];"
        : "=r"(r[0]), "=r"(r[1]), "=r"(r[2]), "=r"(r[3]) : "r"(addr));
}
__device__ __forceinline__ void mma16816(float c[4], const uint32_t a[4],
                                         uint32_t b0, uint32_t b1) {
    asm volatile("mma.sync.aligned.m16n8k16.row.col.f32.bf16.bf16.f32 "
        "{%0,%1,%2,%3}, {%4,%5,%6,%7}, {%8,%9}, {%0,%1,%2,%3};"
        : "+f"(c[0]), "+f"(c[1]), "+f"(c[2]), "+f"(c[3])
        : "r"(a[0]), "r"(a[1]), "r"(a[2]), "r"(a[3]), "r"(b0), "r"(b1));
}

// Swizzled byte offset inside a [rows][128 halves] bf16 tile (row stride 256B).
// chunk(8 halves) XOR (row&7) -> conflict-free ldmatrix + STS.64 stores.
__device__ __forceinline__ uint32_t SWZ(int row, int k) {
    return (uint32_t)(row * 256 + ((((k >> 3) ^ (row & 7)) << 4)) + ((k & 7) << 1));
}

// Load f32 tile [nrows][128] from gmem (row stride gstride floats), split into
// hi/lo bf16 swizzled smem tiles.  nthreads = blockDim.x
__device__ __forceinline__ void load_split_tile(const float* __restrict__ src, int gstride,
                                                int nrows, char* hi, char* lo,
                                                int tid, int nthreads, float scale) {
    const int nf4 = nrows * 32;
    for (int f4 = tid; f4 < nf4; f4 += nthreads) {
        int row = f4 >> 5, k = (f4 & 31) * 4;
        float4 v = *(const float4*)(src + (size_t)row * gstride + k);
        v.x *= scale; v.y *= scale; v.z *= scale; v.w *= scale;
        uint32_t hp0 = pack_bf2(v.x, v.y);
        uint32_t hp1 = pack_bf2(v.z, v.w);
        float h0 = __uint_as_float(hp0 << 16);
        float h1 = __uint_as_float(hp0 & 0xFFFF0000u);
        float h2 = __uint_as_float(hp1 << 16);
        float h3 = __uint_as_float(hp1 & 0xFFFF0000u);
        uint32_t lp0 = pack_bf2(v.x - h0, v.y - h1);
        uint32_t lp1 = pack_bf2(v.z - h2, v.w - h3);
        uint32_t off = SWZ(row, k);
        *(uint2*)(hi + off) = make_uint2(hp0, hp1);
        *(uint2*)(lo + off) = make_uint2(lp0, lp1);
    }
}

// ldmatrix x4 address: tile base (smem u32), frag row origin r0 (mult of 16 or 8-row n-tile
// pairs), kstep ks (k0 = ks*16).  Per-lane invariants passed in.
__device__ __forceinline__ uint32_t lds_addr(uint32_t base, int r0, int ks,
                                             int rowb, int xr, int kq) {
    return base + (uint32_t)(r0 * 256 + rowb + ((((ks * 2) + kq) ^ xr) << 4));
}

// ---------------------------------------------------------------------------
// Kernel: transpose V into [bh][d][t]
// ---------------------------------------------------------------------------
__global__ void transpose_v_kernel(const float* __restrict__ v) {
    __shared__ float tile[32][33];
    const int t0 = blockIdx.x * 32;
    const int bh = blockIdx.y;
    const float* src = v + (size_t)bh * TT * DD;
    float* dst = g_vT + (size_t)bh * DD * TT;
    const int tid = threadIdx.x;
    for (int d0 = 0; d0 < DD; d0 += 32) {
        #pragma unroll
        for (int i = 0; i < 4; i++) {
            int idx = i * 256 + tid;
            int r = idx >> 5, c = idx & 31;
            tile[r][c] = src[(size_t)(t0 + r) * DD + d0 + c];
        }
        __syncthreads();
        #pragma unroll
        for (int i = 0; i < 4; i++) {
            int idx = i * 256 + tid;
            int r = idx >> 5, c = idx & 31;
            dst[(size_t)(d0 + r) * TT + t0 + c] = tile[c][r];
        }
        __syncthreads();
    }
}

// ---------------------------------------------------------------------------
// Kernel: feature attention (CUDA-core f32x2; ~80us, not the bottleneck)
// ---------------------------------------------------------------------------
__device__ __forceinline__ u64t pk2(float lo, float hi) {
    u64t r; asm("mov.b64 %0, {%1, %2};" : "=l"(r) : "f"(lo), "f"(hi)); return r;
}
__device__ __forceinline__ void fma2(u64t& d, u64t a, u64t b) {
    asm("fma.rn.f32x2 %0, %1, %2, %0;" : "+l"(d) : "l"(a), "l"(b));
}
__device__ __forceinline__ void up2(u64t v, float& a, float& b) {
    asm("mov.b64 {%0, %1}, %2;" : "=f"(a), "=f"(b) : "l"(v));
}

__global__ void __launch_bounds__(256) feature_attn_kernel(
    const float* __restrict__ qf, const float* __restrict__ kf,
    float* __restrict__ attn_f) {
    __shared__ float qs[32 * 34];
    __shared__ float ks[32 * 132];
    __shared__ float Sf[32 * 132];

    const int bh = blockIdx.y;
    const int d0blk = blockIdx.x * 32;
    const float* q = qf + (size_t)bh * TT * DD;
    const float* k = kf + (size_t)bh * TT * DD;
    const int tid = threadIdx.x;
    const int ty = tid >> 4, tx = tid & 15;
    const int r0 = ty * 2;
    const int e0 = tx * 8;

    u64t acc[2][4];
    #pragma unroll
    for (int i = 0; i < 2; i++)
        #pragma unroll
        for (int j = 0; j < 4; j++) acc[i][j] = 0ull;

    for (int tt = 0; tt < TT; tt += 32) {
        #pragma unroll
        for (int i = 0; i < 4; i++) {
            int idx = i * 256 + tid;
            int r = idx >> 5, c = idx & 31;
            qs[r * 34 + c] = q[(size_t)(tt + r) * DD + d0blk + c] * INV_TEMP;
        }
        #pragma unroll
        for (int i = 0; i < 4; i++) {
            int idx = i * 256 + tid;
            int r = idx >> 5, c4 = (idx & 31) * 4;
            *(float4*)&ks[r * 132 + c4] = *(const float4*)&k[(size_t)(tt + r) * DD + c4];
        }
        __syncthreads();
        #pragma unroll 4
        for (int t = 0; t < 32; t++) {
            float2 a = *(float2*)&qs[t * 34 + r0];
            ulonglong2 b0 = *(ulonglong2*)&ks[t * 132 + e0];
            ulonglong2 b1 = *(ulonglong2*)&ks[t * 132 + e0 + 4];
            u64t a0 = pk2(a.x, a.x), a1 = pk2(a.y, a.y);
            fma2(acc[0][0], a0, b0.x); fma2(acc[0][1], a0, b0.y);
            fma2(acc[0][2], a0, b1.x); fma2(acc[0][3], a0, b1.y);
            fma2(acc[1][0], a1, b0.x); fma2(acc[1][1], a1, b0.y);
            fma2(acc[1][2], a1, b1.x); fma2(acc[1][3], a1, b1.y);
        }
        __syncthreads();
    }

    #pragma unroll
    for (int i = 0; i < 2; i++) {
        float x[8];
        up2(acc[i][0], x[0], x[1]); up2(acc[i][1], x[2], x[3]);
        up2(acc[i][2], x[4], x[5]); up2(acc[i][3], x[6], x[7]);
        *(float4*)&Sf[(r0 + i) * 132 + e0]     = make_float4(x[0], x[1], x[2], x[3]);
        *(float4*)&Sf[(r0 + i) * 132 + e0 + 4] = make_float4(x[4], x[5], x[6], x[7]);
    }
    __syncthreads();

    const int lane = tid & 31, w = tid >> 5;
    float* af = attn_f + (size_t)bh * DD * DD;
    #pragma unroll
    for (int rr = 0; rr < 4; rr++) {
        int r = w * 4 + rr;
        float vv[4], mx = -1e30f;
        #pragma unroll
        for (int kk = 0; kk < 4; kk++) {
            vv[kk] = Sf[r * 132 + lane + 32 * kk];
            mx = fmaxf(mx, vv[kk]);
        }
        #pragma unroll
        for (int o = 16; o; o >>= 1) mx = fmaxf(mx, __shfl_xor_sync(~0u, mx, o));
        float ssum = 0.f;
        #pragma unroll
        for (int kk = 0; kk < 4; kk++) { vv[kk] = __expf(vv[kk] - mx); ssum += vv[kk]; }
        #pragma unroll
        for (int o = 16; o; o >>= 1) ssum += __shfl_xor_sync(~0u, ssum, o);
        float iv = 1.0f / ssum;
        #pragma unroll
        for (int kk = 0; kk < 4; kk++)
            af[(size_t)(d0blk + r) * DD + lane + 32 * kk] = vv[kk] * iv;
    }
}

// ---------------------------------------------------------------------------
// Kernel: transpose attn_feature into g_ft [bh][e][d]
// ---------------------------------------------------------------------------
__global__ void ft_transpose_kernel(const float* __restrict__ af) {
    __shared__ float tile[32][33];
    const int e0 = blockIdx.x * 32;
    const int bh = blockIdx.y;
    const float* src = af + (size_t)bh * DD * DD;
    float* dst = g_ft + (size_t)bh * DD * DD;
    const int tid = threadIdx.x;
    for (int d0 = 0; d0 < DD; d0 += 32) {
        #pragma unroll
        for (int i = 0; i < 4; i++) {
            int idx = i * 256 + tid;
            int r = idx >> 5, c = idx & 31;
            tile[r][c] = src[(size_t)(d0 + r) * DD + e0 + c];
        }
        __syncthreads();
        #pragma unroll
        for (int i = 0; i < 4; i++) {
            int idx = i * 256 + tid;
            int r = idx >> 5, c = idx & 31;
            dst[(size_t)(e0 + r) * DD + d0 + c] = tile[c][r];
        }
        __syncthreads();
    }
}

// ---------------------------------------------------------------------------
// Kernel S: time scores via mma.sync bf16 split + exp + rowsum + normalize.
// grid (8, 64), block 512 (16 warps: warp_m = wid&1, warp_n = wid>>1).
// CTA: 128 rows x 1024 cols, col-chunked by 128.  Warp tile 64x16.
// smem: QH|QL (q tile, resident) + BH|BL (k_time chunk) + red/inv.
// ---------------------------------------------------------------------------
#define S_QH 0
#define S_QL 32768
#define S_BH 65536
#define S_BL 98304
#define S_RED 131072
#define S_INV 131584
#define S_SMEM 132096

__global__ void __launch_bounds__(512, 1) score_mma_kernel(
    const float* __restrict__ q_time, const float* __restrict__ k_time,
    float* __restrict__ attn_t) {
    extern __shared__ char sm[];
    const uint32_t sb = smem_u32(sm);
    float* red  = (float*)(sm + S_RED);
    float* invs = (float*)(sm + S_INV);

    const int bh = blockIdx.y;
    const int r0 = blockIdx.x * 128;
    const int tid = threadIdx.x;
    const int wid = tid >> 5, lane = tid & 31;
    const int warp_m = wid & 1, warp_n = wid >> 1;
    const int g = lane >> 2, tig = lane & 3;

    // ldmatrix per-lane invariants
    const int rA = (lane & 7) + ((lane >> 3) & 1) * 8;
    const int rowb = rA * 256;
    const int xr = rA & 7;
    const int kq = lane >> 4;

    if (tid < 128) red[tid] = 0.f;

    // resident Q tile (scaled)
    load_split_tile(q_time + ((size_t)bh * TT + r0) * DD, DD, 128,
                    sm + S_QH, sm + S_QL, tid, 512, INV_TEMP);

    const float* kbase = k_time + (size_t)bh * TT * DD;
    float* E = attn_t + ((size_t)bh * TT + r0) * TT;

    float rsum[8] = {0, 0, 0, 0, 0, 0, 0, 0};

    for (int c = 0; c < 8; c++) {
        __syncthreads();
        load_split_tile(kbase + (size_t)c * 128 * DD, DD, 128,
                        sm + S_BH, sm + S_BL, tid, 512, 1.f);
        __syncthreads();

        float acc[4][2][4];
        #pragma unroll
        for (int mi = 0; mi < 4; mi++)
            #pragma unroll
            for (int nf = 0; nf < 2; nf++)
                #pragma unroll
                for (int j = 0; j < 4; j++) acc[mi][nf][j] = 0.f;

        #pragma unroll
        for (int ksi = 0; ksi < 8; ksi++) {
            uint32_t ah[4][4], al[4][4], bhv[4], blv[4];
            #pragma unroll
            for (int mi = 0; mi < 4; mi++) {
                int fr = warp_m * 64 + mi * 16;
                ldsm4(lds_addr(sb + S_QH, fr, ksi, rowb, xr, kq), ah[mi]);
                ldsm4(lds_addr(sb + S_QL, fr, ksi, rowb, xr, kq), al[mi]);
            }
            {
                int nr = warp_n * 16;
                ldsm4(lds_addr(sb + S_BH, nr, ksi, rowb, xr, kq), bhv);
                ldsm4(lds_addr(sb + S_BL, nr, ksi, rowb, xr, kq), blv);
            }
            #pragma unroll
            for (int mi = 0; mi < 4; mi++) {
                mma16816(acc[mi][0], ah[mi], bhv[0], bhv[2]);
                mma16816(acc[mi][1], ah[mi], bhv[1], bhv[3]);
                mma16816(acc[mi][0], ah[mi], blv[0], blv[2]);
                mma16816(acc[mi][1], ah[mi], blv[1], blv[3]);
                mma16816(acc[mi][0], al[mi], bhv[0], bhv[2]);
                mma16816(acc[mi][1], al[mi], bhv[1], bhv[3]);
            }
        }

        // epilogue: exp, rowsum, store unnormalized E
        #pragma unroll
        for (int mi = 0; mi < 4; mi++) {
            int rowA = warp_m * 64 + mi * 16 + g;
            #pragma unroll
            for (int nf = 0; nf < 2; nf++) {
                float e0 = __expf(acc[mi][nf][0]);
                float e1 = __expf(acc[mi][nf][1]);
                float e2 = __expf(acc[mi][nf][2]);
                float e3 = __expf(acc[mi][nf][3]);
                rsum[mi * 2 + 0] += e0 + e1;
                rsum[mi * 2 + 1] += e2 + e3;
                int col = c * 128 + warp_n * 16 + nf * 8 + tig * 2;
                *(float2*)&E[(size_t)rowA * TT + col]       = make_float2(e0, e1);
                *(float2*)&E[(size_t)(rowA + 8) * TT + col] = make_float2(e2, e3);
            }
        }
    }

    // reduce rowsums: over tig lanes, then atomics across warp_n warps
    #pragma unroll
    for (int j = 0; j < 8; j++) {
        rsum[j] += __shfl_xor_sync(~0u, rsum[j], 1);
        rsum[j] += __shfl_xor_sync(~0u, rsum[j], 2);
    }
    if (tig == 0) {
        #pragma unroll
        for (int mi = 0; mi < 4; mi++) {
            int rowA = warp_m * 64 + mi * 16 + g;
            atomicAdd(&red[rowA],     rsum[mi * 2 + 0]);
            atomicAdd(&red[rowA + 8], rsum[mi * 2 + 1]);
        }
    }
    __syncthreads();
    if (tid < 128) invs[tid] = 1.0f / red[tid];
    __syncthreads();

    // normalize pass (L2-hot re-read of this CTA's 512KB)
    float4* E4 = (float4*)E;
    #pragma unroll 4
    for (int it = 0; it < 64; it++) {
        int f = it * 512 + tid;
        int row = f >> 8, c4 = f & 255;
        float iv = invs[row];
        float4 vv = E4[(size_t)row * 256 + c4];
        vv.x *= iv; vv.y *= iv; vv.z *= iv; vv.w *= iv;
        E4[(size_t)row * 256 + c4] = vv;
    }
}

// ---------------------------------------------------------------------------
// Kernel T: tv = attn_time @ V  (K=1024 chunked by 128), then out = tv @ F^T.
// grid (8, 64), block 512 (16 warps), warp tile 64x16.
// smem: AH|AL (attn chunk / tv tile) + BH|BL (vT chunk / ft tile).
// ---------------------------------------------------------------------------
#define T_AH 0
#define T_AL 32768
#define T_BH 65536
#define T_BL 98304
#define T_SMEM 131072

__global__ void __launch_bounds__(512, 1) tv_out_mma_kernel(
    const float* __restrict__ attn_t, float* __restrict__ out) {
    extern __shared__ char sm[];
    const uint32_t sb = smem_u32(sm);

    const int bh = blockIdx.y;
    const int r0 = blockIdx.x * 128;
    const int tid = threadIdx.x;
    const int wid = tid >> 5, lane = tid & 31;
    const int warp_m = wid & 1, warp_n = wid >> 1;
    const int g = lane >> 2, tig = lane & 3;

    const int rA = (lane & 7) + ((lane >> 3) & 1) * 8;
    const int rowb = rA * 256;
    const int xr = rA & 7;
    const int kq = lane >> 4;

    const float* A = attn_t + ((size_t)bh * TT + r0) * TT;
    const float* BvT = g_vT + (size_t)bh * DD * TT;

    float acc[4][2][4];
    #pragma unroll
    for (int mi = 0; mi < 4; mi++)
        #pragma unroll
        for (int nf = 0; nf < 2; nf++)
            #pragma unroll
            for (int j = 0; j < 4; j++) acc[mi][nf][j] = 0.f;

    // ---- GEMM2: tv = A @ V  (B = vT rows = d, col-major k=s) ----
    for (int kc = 0; kc < 8; kc++) {
        __syncthreads();
        load_split_tile(A + (size_t)kc * 128, TT, 128, sm + T_AH, sm + T_AL, tid, 512, 1.f);
        load_split_tile(BvT + (size_t)kc * 128, TT, 128, sm + T_BH, sm + T_BL, tid, 512, 1.f);
        __syncthreads();

        #pragma unroll
        for (int ksi = 0; ksi < 8; ksi++) {
            uint32_t ah[4][4], al[4][4], bhv[4], blv[4];
            #pragma unroll
            for (int mi = 0; mi < 4; mi++) {
                int fr = warp_m * 64 + mi * 16;
                ldsm4(lds_addr(sb + T_AH, fr, ksi, rowb, xr, kq), ah[mi]);
                ldsm4(lds_addr(sb + T_AL, fr, ksi, rowb, xr, kq), al[mi]);
            }
            {
                int nr = warp_n * 16;
                ldsm4(lds_addr(sb + T_BH, nr, ksi, rowb, xr, kq), bhv);
                ldsm4(lds_addr(sb + T_BL, nr, ksi, rowb, xr, kq), blv);
            }
            #pragma unroll
            for (int mi = 0; mi < 4; mi++) {
                mma16816(acc[mi][0], ah[mi], bhv[0], bhv[2]);
                mma16816(acc[mi][1], ah[mi], bhv[1], bhv[3]);
                mma16816(acc[mi][0], ah[mi], blv[0], blv[2]);
                mma16816(acc[mi][1], ah[mi], blv[1], blv[3]);
                mma16816(acc[mi][0], al[mi], bhv[0], bhv[2]);
                mma16816(acc[mi][1], al[mi], bhv[1], bhv[3]);
            }
        }
    }

    // ---- stage tv into smem A-region as split bf16 (swizzled) ----
    __syncthreads();
    {
        char* th = sm + T_AH;
        char* tl = sm + T_AL;
        #pragma unroll
        for (int mi = 0; mi < 4; mi++) {
            int rowA = warp_m * 64 + mi * 16 + g;
            #pragma unroll
            for (int nf = 0; nf < 2; nf++) {
                int d0 = warp_n * 16 + nf * 8 + tig * 2;
                float v0 = acc[mi][nf][0], v1 = acc[mi][nf][1];
                float v2 = acc[mi][nf][2], v3 = acc[mi][nf][3];
                uint32_t hp0 = pack_bf2(v0, v1);
                uint32_t hp1 = pack_bf2(v2, v3);
                float h0 = __uint_as_float(hp0 << 16);
                float h1 = __uint_as_float(hp0 & 0xFFFF0000u);
                float h2 = __uint_as_float(hp1 << 16);
                float h3 = __uint_as_float(hp1 & 0xFFFF0000u);
                uint32_t lp0 = pack_bf2(v0 - h0, v1 - h1);
                uint32_t lp1 = pack_bf2(v2 - h2, v3 - h3);
                *(uint32_t*)(th + SWZ(rowA, d0))     = hp0;
                *(uint32_t*)(tl + SWZ(rowA, d0))     = lp0;
                *(uint32_t*)(th + SWZ(rowA + 8, d0)) = hp1;
                *(uint32_t*)(tl + SWZ(rowA + 8, d0)) = lp1;
            }
        }
    }
    // ---- load F^T (g_ft rows = e, col-major k=d) into B-region ----
    load_split_tile(g_ft + (size_t)bh * DD * DD, DD, 128, sm + T_BH, sm + T_BL, tid, 512, 1.f);
    __syncthreads();

    // ---- GEMM3: out = tv @ F^T, single K=128 pass ----
    float acc3[4][2][4];
    #pragma unroll
    for (int mi = 0; mi < 4; mi++)
        #pragma unroll
        for (int nf = 0; nf < 2; nf++)
            #pragma unroll
            for (int j = 0; j < 4; j++) acc3[mi][nf][j] = 0.f;

    #pragma unroll
    for (int ksi = 0; ksi < 8; ksi++) {
        uint32_t ah[4][4], al[4][4], bhv[4], blv[4];
        #pragma unroll
        for (int mi = 0; mi < 4; mi++) {
            int fr = warp_m * 64 + mi * 16;
            ldsm4(lds_addr(sb + T_AH, fr, ksi, rowb, xr, kq), ah[mi]);
            ldsm4(lds_addr(sb + T_AL, fr, ksi, rowb, xr, kq), al[mi]);
        }
        {
            int nr = warp_n * 16;
            ldsm4(lds_addr(sb + T_BH, nr, ksi, rowb, xr, kq), bhv);
            ldsm4(lds_addr(sb + T_BL, nr, ksi, rowb, xr, kq), blv);
        }
        #pragma unroll
        for (int mi = 0; mi < 4; mi++) {
            mma16816(acc3[mi][0], ah[mi], bhv[0], bhv[2]);
            mma16816(acc3[mi][1], ah[mi], bhv[1], bhv[3]);
            mma16816(acc3[mi][0], ah[mi], blv[0], blv[2]);
            mma16816(acc3[mi][1], ah[mi], blv[1], blv[3]);
            mma16816(acc3[mi][0], al[mi], bhv[0], bhv[2]);
            mma16816(acc3[mi][1], al[mi], bhv[1], bhv[3]);
        }
    }

    float* op = out + ((size_t)bh * TT + r0) * DD;
    #pragma unroll
    for (int mi = 0; mi < 4; mi++) {
        int rowA = warp_m * 64 + mi * 16 + g;
        #pragma unroll
        for (int nf = 0; nf < 2; nf++) {
            int e = warp_n * 16 + nf * 8 + tig * 2;
            *(float2*)&op[(size_t)rowA * DD + e] =
                make_float2(acc3[mi][nf][0], acc3[mi][nf][1]);
            *(float2*)&op[(size_t)(rowA + 8) * DD + e] =
                make_float2(acc3[mi][nf][2], acc3[mi][nf][3]);
        }
    }
}

// ---------------------------------------------------------------------------
// Launch
// ---------------------------------------------------------------------------
extern "C" void kernel_launch(void* const* d_in, const int* in_sizes, int n_in,
                              void* d_out, int out_size) {
    const float* q_time    = (const float*)d_in[0];
    const float* k_time    = (const float*)d_in[1];
    const float* q_feature = (const float*)d_in[2];
    const float* k_feature = (const float*)d_in[3];
    const float* v         = (const float*)d_in[4];

    float* out    = (float*)d_out;                       // [BH][T][D]
    float* attn_t = out + (size_t)BHN * TT * DD;         // [BH][T][T]
    float* attn_f = attn_t + (size_t)BHN * TT * TT;      // [BH][D][D]

    cudaFuncSetAttribute(score_mma_kernel,
                         cudaFuncAttributeMaxDynamicSharedMemorySize, S_SMEM);
    cudaFuncSetAttribute(tv_out_mma_kernel,
                         cudaFuncAttributeMaxDynamicSharedMemorySize, T_SMEM);

    transpose_v_kernel<<<dim3(TT / 32, BHN), 256>>>(v);
    feature_attn_kernel<<<dim3(4, BHN), 256>>>(q_feature, k_feature, attn_f);
    ft_transpose_kernel<<<dim3(4, BHN), 256>>>(attn_f);
    score_mma_kernel<<<dim3(TT / 128, BHN), 512, S_SMEM>>>(q_time, k_time, attn_t);
    tv_out_mma_kernel<<<dim3(TT / 128, BHN), 512, T_SMEM>>>(attn_t, out);
}

// round 6
// speedup vs baseline: 3.2113x; 1.0928x over previous
#include <cuda_runtime.h>
#include <cuda_bf16.h>
#include <cstdint>

// Problem constants
#define BHN 64          // B*H
#define TT 1024         // sequence length
#define DD 128          // head dim
static __device__ __constant__ float INV_TEMP = 0.08838834764831845f;  // 1/sqrt(128)

// ---------------------------------------------------------------------------
// Pre-split bf16 scratch (hi/lo pairs). Layouts noted per array.
// ---------------------------------------------------------------------------
__device__ __align__(16) unsigned char g_qh[(size_t)BHN * TT * DD * 2];  // [bh][t][d] (scaled)
__device__ __align__(16) unsigned char g_ql[(size_t)BHN * TT * DD * 2];
__device__ __align__(16) unsigned char g_kh[(size_t)BHN * TT * DD * 2];  // [bh][t][d]
__device__ __align__(16) unsigned char g_kl[(size_t)BHN * TT * DD * 2];
__device__ __align__(16) unsigned char g_vh[(size_t)BHN * DD * TT * 2];  // [bh][d][t]
__device__ __align__(16) unsigned char g_vl[(size_t)BHN * DD * TT * 2];
__device__ __align__(16) unsigned char g_fh[(size_t)BHN * DD * DD * 2];  // [bh][e][d]
__device__ __align__(16) unsigned char g_fl[(size_t)BHN * DD * DD * 2];
__device__ __align__(16) unsigned char g_eh[(size_t)BHN * TT * TT * 2];  // [bh][t][s] unnormalized exp
__device__ __align__(16) unsigned char g_el[(size_t)BHN * TT * TT * 2];
__device__ float g_inv[BHN * TT];

typedef unsigned long long u64t;

// ---------------------------------------------------------------------------
// helpers
// ---------------------------------------------------------------------------
__device__ __forceinline__ uint32_t smem_u32(const void* p) {
    uint32_t a;
    asm("{ .reg .u64 t; cvta.to.shared.u64 t, %1; cvt.u32.u64 %0, t; }" : "=r"(a) : "l"(p));
    return a;
}
// pack two f32 to bf16x2: low half = first arg
__device__ __forceinline__ uint32_t pack_bf2(float lo, float hi) {
    uint32_t r;
    asm("cvt.rn.bf16x2.f32 %0, %1, %2;" : "=r"(r) : "f"(hi), "f"(lo));
    return r;
}
// split two f32 into (hi bf16x2, lo bf16x2)
__device__ __forceinline__ void split2(float v0, float v1, uint32_t& hp, uint32_t& lp) {
    hp = pack_bf2(v0, v1);
    float h0 = __uint_as_float(hp << 16);
    float h1 = __uint_as_float(hp & 0xFFFF0000u);
    lp = pack_bf2(v0 - h0, v1 - h1);
}
__device__ __forceinline__ float join2(uint32_t hp, uint32_t lp, int which) {
    float h = which ? __uint_as_float(hp & 0xFFFF0000u) : __uint_as_float(hp << 16);
    float l = which ? __uint_as_float(lp & 0xFFFF0000u) : __uint_as_float(lp << 16);
    return h + l;
}
__device__ __forceinline__ void ldsm4(uint32_t addr, uint32_t r[4]) {
    asm volatile("ldmatrix.sync.aligned.m8n8.x4.shared.b16 {%0,%1,%2,%3}, [%4];"
        : "=r"(r[0]), "=r"(r[1]), "=r"(r[2]), "=r"(r[3]) : "r"(addr));
}
__device__ __forceinline__ void mma16816(float c[4], const uint32_t a[4],
                                         uint32_t b0, uint32_t b1) {
    asm volatile("mma.sync.aligned.m16n8k16.row.col.f32.bf16.bf16.f32 "
        "{%0,%1,%2,%3}, {%4,%5,%6,%7}, {%8,%9}, {%0,%1,%2,%3};"
        : "+f"(c[0]), "+f"(c[1]), "+f"(c[2]), "+f"(c[3])
        : "r"(a[0]), "r"(a[1]), "r"(a[2]), "r"(a[3]), "r"(b0), "r"(b1));
}
__device__ __forceinline__ void cpasync16(uint32_t dst, const void* src) {
    asm volatile("cp.async.cg.shared.global [%0], [%1], 16;" :: "r"(dst), "l"(src));
}
#define CP_COMMIT() asm volatile("cp.async.commit_group;" ::: "memory")
#define CP_WAIT1()  asm volatile("cp.async.wait_group 1;" ::: "memory")
#define CP_WAIT0()  asm volatile("cp.async.wait_group 0;" ::: "memory")

// TILE64: [128 rows][64 bf16], row stride 128B, 8x 16B chunks XOR-swizzled by row&7.
__device__ __forceinline__ uint32_t SWZ64(int row, int k) {
    return (uint32_t)(row * 128 + ((((k >> 3) ^ (row & 7)) << 4)) + ((k & 7) << 1));
}
// ldmatrix x4 address into a TILE64: frag row origin fr, kstep ksi (16 halves each)
__device__ __forceinline__ uint32_t a64(uint32_t base, int fr, int ksi,
                                        int rA, int xr, int kq) {
    return base + (uint32_t)((fr + rA) * 128 + (((ksi * 2 + kq) ^ xr) << 4));
}
// async-load one TILE64 from gmem (row stride bytes). 512-thread blocks only.
__device__ __forceinline__ void load_tile_async(uint32_t tile, const unsigned char* src,
                                                int stride, int tid) {
    #pragma unroll
    for (int i = 0; i < 2; i++) {
        int idx = i * 512 + tid;
        int row = idx >> 3, ch = idx & 7;
        cpasync16(tile + row * 128 + ((ch ^ (row & 7)) << 4),
                  src + (size_t)row * stride + ch * 16);
    }
}

// ---------------------------------------------------------------------------
// Prep kernels
// ---------------------------------------------------------------------------
// q_time (scaled) and k_time -> hi/lo bf16, layout preserved. grid (8192, 2), blk 256.
__global__ void qk_split_kernel(const float* __restrict__ q, const float* __restrict__ k) {
    const bool isq = (blockIdx.y == 0);
    const float* src = isq ? q : k;
    unsigned char* hi = isq ? g_qh : g_kh;
    unsigned char* lo = isq ? g_ql : g_kl;
    const float scale = isq ? INV_TEMP : 1.0f;
    size_t i4 = (size_t)blockIdx.x * 256 + threadIdx.x;
    float4 v = ((const float4*)src)[i4];
    v.x *= scale; v.y *= scale; v.z *= scale; v.w *= scale;
    uint32_t hp0, lp0, hp1, lp1;
    split2(v.x, v.y, hp0, lp0);
    split2(v.z, v.w, hp1, lp1);
    ((uint2*)hi)[i4] = make_uint2(hp0, hp1);
    ((uint2*)lo)[i4] = make_uint2(lp0, lp1);
}

// V [bh][t][d] -> transposed split [bh][d][t]. grid (32, 64), blk 256.
__global__ void v_split_T_kernel(const float* __restrict__ v) {
    __shared__ float tile[32][33];
    const int t0 = blockIdx.x * 32;
    const int bh = blockIdx.y;
    const float* src = v + (size_t)bh * TT * DD;
    unsigned char* dh = g_vh + (size_t)bh * DD * TT * 2;
    unsigned char* dl = g_vl + (size_t)bh * DD * TT * 2;
    const int tid = threadIdx.x;
    for (int d0 = 0; d0 < DD; d0 += 32) {
        #pragma unroll
        for (int i = 0; i < 4; i++) {
            int idx = i * 256 + tid;
            int r = idx >> 5, c = idx & 31;
            tile[r][c] = src[(size_t)(t0 + r) * DD + d0 + c];
        }
        __syncthreads();
        #pragma unroll
        for (int i = 0; i < 2; i++) {
            int idx = i * 256 + tid;
            int r = idx >> 4, c2 = (idx & 15) * 2;   // r: d-local, c2: t-local pair
            float v0 = tile[c2][r], v1 = tile[c2 + 1][r];
            uint32_t hp, lp;
            split2(v0, v1, hp, lp);
            size_t off = ((size_t)(d0 + r) * TT + t0 + c2) * 2;
            *(uint32_t*)(dh + off) = hp;
            *(uint32_t*)(dl + off) = lp;
        }
        __syncthreads();
    }
}

// attn_f [bh][d][e] -> transposed split [bh][e][d]. grid (4, 64), blk 256.
__global__ void ft_split_T_kernel(const float* __restrict__ af) {
    __shared__ float tile[32][33];
    const int e0 = blockIdx.x * 32;
    const int bh = blockIdx.y;
    const float* src = af + (size_t)bh * DD * DD;
    unsigned char* dh = g_fh + (size_t)bh * DD * DD * 2;
    unsigned char* dl = g_fl + (size_t)bh * DD * DD * 2;
    const int tid = threadIdx.x;
    for (int d0 = 0; d0 < DD; d0 += 32) {
        #pragma unroll
        for (int i = 0; i < 4; i++) {
            int idx = i * 256 + tid;
            int r = idx >> 5, c = idx & 31;   // r: d-local, c: e-local
            tile[r][c] = src[(size_t)(d0 + r) * DD + e0 + c];
        }
        __syncthreads();
        #pragma unroll
        for (int i = 0; i < 2; i++) {
            int idx = i * 256 + tid;
            int r = idx >> 4, c2 = (idx & 15) * 2;   // r: e-local, c2: d-local pair
            float v0 = tile[c2][r], v1 = tile[c2 + 1][r];
            uint32_t hp, lp;
            split2(v0, v1, hp, lp);
            size_t off = ((size_t)(e0 + r) * DD + d0 + c2) * 2;
            *(uint32_t*)(dh + off) = hp;
            *(uint32_t*)(dl + off) = lp;
        }
        __syncthreads();
    }
}

// ---------------------------------------------------------------------------
// Feature attention (CUDA-core f32x2; not the bottleneck)
// ---------------------------------------------------------------------------
__device__ __forceinline__ u64t pk2(float lo, float hi) {
    u64t r; asm("mov.b64 %0, {%1, %2};" : "=l"(r) : "f"(lo), "f"(hi)); return r;
}
__device__ __forceinline__ void fma2(u64t& d, u64t a, u64t b) {
    asm("fma.rn.f32x2 %0, %1, %2, %0;" : "+l"(d) : "l"(a), "l"(b));
}
__device__ __forceinline__ void up2(u64t v, float& a, float& b) {
    asm("mov.b64 {%0, %1}, %2;" : "=f"(a), "=f"(b) : "l"(v));
}

__global__ void __launch_bounds__(256) feature_attn_kernel(
    const float* __restrict__ qf, const float* __restrict__ kf,
    float* __restrict__ attn_f) {
    __shared__ float qs[32 * 34];
    __shared__ float ks[32 * 132];
    __shared__ float Sf[32 * 132];

    const int bh = blockIdx.y;
    const int d0blk = blockIdx.x * 32;
    const float* q = qf + (size_t)bh * TT * DD;
    const float* k = kf + (size_t)bh * TT * DD;
    const int tid = threadIdx.x;
    const int ty = tid >> 4, tx = tid & 15;
    const int r0 = ty * 2;
    const int e0 = tx * 8;

    u64t acc[2][4];
    #pragma unroll
    for (int i = 0; i < 2; i++)
        #pragma unroll
        for (int j = 0; j < 4; j++) acc[i][j] = 0ull;

    for (int tt = 0; tt < TT; tt += 32) {
        #pragma unroll
        for (int i = 0; i < 4; i++) {
            int idx = i * 256 + tid;
            int r = idx >> 5, c = idx & 31;
            qs[r * 34 + c] = q[(size_t)(tt + r) * DD + d0blk + c] * INV_TEMP;
        }
        #pragma unroll
        for (int i = 0; i < 4; i++) {
            int idx = i * 256 + tid;
            int r = idx >> 5, c4 = (idx & 31) * 4;
            *(float4*)&ks[r * 132 + c4] = *(const float4*)&k[(size_t)(tt + r) * DD + c4];
        }
        __syncthreads();
        #pragma unroll 4
        for (int t = 0; t < 32; t++) {
            float2 a = *(float2*)&qs[t * 34 + r0];
            ulonglong2 b0 = *(ulonglong2*)&ks[t * 132 + e0];
            ulonglong2 b1 = *(ulonglong2*)&ks[t * 132 + e0 + 4];
            u64t a0 = pk2(a.x, a.x), a1 = pk2(a.y, a.y);
            fma2(acc[0][0], a0, b0.x); fma2(acc[0][1], a0, b0.y);
            fma2(acc[0][2], a0, b1.x); fma2(acc[0][3], a0, b1.y);
            fma2(acc[1][0], a1, b0.x); fma2(acc[1][1], a1, b0.y);
            fma2(acc[1][2], a1, b1.x); fma2(acc[1][3], a1, b1.y);
        }
        __syncthreads();
    }

    #pragma unroll
    for (int i = 0; i < 2; i++) {
        float x[8];
        up2(acc[i][0], x[0], x[1]); up2(acc[i][1], x[2], x[3]);
        up2(acc[i][2], x[4], x[5]); up2(acc[i][3], x[6], x[7]);
        *(float4*)&Sf[(r0 + i) * 132 + e0]     = make_float4(x[0], x[1], x[2], x[3]);
        *(float4*)&Sf[(r0 + i) * 132 + e0 + 4] = make_float4(x[4], x[5], x[6], x[7]);
    }
    __syncthreads();

    const int lane = tid & 31, w = tid >> 5;
    float* af = attn_f + (size_t)bh * DD * DD;
    #pragma unroll
    for (int rr = 0; rr < 4; rr++) {
        int r = w * 4 + rr;
        float vv[4], mx = -1e30f;
        #pragma unroll
        for (int kk = 0; kk < 4; kk++) {
            vv[kk] = Sf[r * 132 + lane + 32 * kk];
            mx = fmaxf(mx, vv[kk]);
        }
        #pragma unroll
        for (int o = 16; o; o >>= 1) mx = fmaxf(mx, __shfl_xor_sync(~0u, mx, o));
        float ssum = 0.f;
        #pragma unroll
        for (int kk = 0; kk < 4; kk++) { vv[kk] = __expf(vv[kk] - mx); ssum += vv[kk]; }
        #pragma unroll
        for (int o = 16; o; o >>= 1) ssum += __shfl_xor_sync(~0u, ssum, o);
        float iv = 1.0f / ssum;
        #pragma unroll
        for (int kk = 0; kk < 4; kk++)
            af[(size_t)(d0blk + r) * DD + lane + 32 * kk] = vv[kk] * iv;
    }
}

// ---------------------------------------------------------------------------
// Kernel S: scores via mma.sync (pre-split operands, cp.async double-buffer).
// grid (8, 64), block 512 (warp_m = wid&1, warp_n = wid>>1), warp tile 64x16.
// Writes E hi/lo bf16 + g_inv + normalized attn_time f32.
// ---------------------------------------------------------------------------
#define S_Q   0                     // QH0,QH1,QL0,QL1 (16KB each)
#define S_B   65536                 // 2 bufs x (BH0,BH1,BL0,BL1)
#define S_RED (65536 + 131072)
#define S_INV (S_RED + 512)
#define S_SMEM (S_INV + 512)

__global__ void __launch_bounds__(512, 1) score_mma_kernel(float* __restrict__ attn_t) {
    extern __shared__ char sm[];
    const uint32_t sb = smem_u32(sm);
    float* red  = (float*)(sm + S_RED);
    float* invs = (float*)(sm + S_INV);

    const int bh = blockIdx.y;
    const int r0 = blockIdx.x * 128;
    const int tid = threadIdx.x;
    const int wid = tid >> 5, lane = tid & 31;
    const int warp_m = wid & 1, warp_n = wid >> 1;
    const int g = lane >> 2, tig = lane & 3;
    const int rA = (lane & 7) + ((lane >> 3) & 1) * 8;
    const int xr = rA & 7, kq = lane >> 4;

    if (tid < 128) red[tid] = 0.f;

    const unsigned char* qh = g_qh + ((size_t)bh * TT + r0) * 256;
    const unsigned char* ql = g_ql + ((size_t)bh * TT + r0) * 256;
    const unsigned char* kh = g_kh + (size_t)bh * TT * 256;
    const unsigned char* kl = g_kl + (size_t)bh * TT * 256;
    unsigned char* ehb = g_eh + ((size_t)bh * TT + r0) * 2048;
    unsigned char* elb = g_el + ((size_t)bh * TT + r0) * 2048;

    // prologue: Q (resident) + B chunk 0
    load_tile_async(sb + S_Q +     0, qh,       256, tid);
    load_tile_async(sb + S_Q + 16384, qh + 128, 256, tid);
    load_tile_async(sb + S_Q + 32768, ql,       256, tid);
    load_tile_async(sb + S_Q + 49152, ql + 128, 256, tid);
    load_tile_async(sb + S_B +     0, kh,       256, tid);
    load_tile_async(sb + S_B + 16384, kh + 128, 256, tid);
    load_tile_async(sb + S_B + 32768, kl,       256, tid);
    load_tile_async(sb + S_B + 49152, kl + 128, 256, tid);
    CP_COMMIT();

    float rsum[8] = {0, 0, 0, 0, 0, 0, 0, 0};

    for (int c = 0; c < 8; c++) {
        if (c < 7) {
            const unsigned char* kh1 = kh + (size_t)(c + 1) * 128 * 256;
            const unsigned char* kl1 = kl + (size_t)(c + 1) * 128 * 256;
            uint32_t bb = sb + S_B + ((c + 1) & 1) * 65536;
            load_tile_async(bb +     0, kh1,       256, tid);
            load_tile_async(bb + 16384, kh1 + 128, 256, tid);
            load_tile_async(bb + 32768, kl1,       256, tid);
            load_tile_async(bb + 49152, kl1 + 128, 256, tid);
            CP_COMMIT();
            CP_WAIT1();
        } else {
            CP_WAIT0();
        }
        __syncthreads();

        const uint32_t qb = sb + S_Q;
        const uint32_t bb = sb + S_B + (c & 1) * 65536;
        float acc[4][2][4];
        #pragma unroll
        for (int mi = 0; mi < 4; mi++)
            #pragma unroll
            for (int nf = 0; nf < 2; nf++)
                #pragma unroll
                for (int j = 0; j < 4; j++) acc[mi][nf][j] = 0.f;

        #pragma unroll
        for (int kt = 0; kt < 2; kt++) {
            #pragma unroll
            for (int ksi = 0; ksi < 4; ksi++) {
                uint32_t ah[4][4], al[4][4], bhv[4], blv[4];
                #pragma unroll
                for (int mi = 0; mi < 4; mi++) {
                    int fr = warp_m * 64 + mi * 16;
                    ldsm4(a64(qb + kt * 16384, fr, ksi, rA, xr, kq), ah[mi]);
                    ldsm4(a64(qb + 32768 + kt * 16384, fr, ksi, rA, xr, kq), al[mi]);
                }
                {
                    int nr = warp_n * 16;
                    ldsm4(a64(bb + kt * 16384, nr, ksi, rA, xr, kq), bhv);
                    ldsm4(a64(bb + 32768 + kt * 16384, nr, ksi, rA, xr, kq), blv);
                }
                #pragma unroll
                for (int mi = 0; mi < 4; mi++) {
                    mma16816(acc[mi][0], ah[mi], bhv[0], bhv[2]);
                    mma16816(acc[mi][1], ah[mi], bhv[1], bhv[3]);
                    mma16816(acc[mi][0], ah[mi], blv[0], blv[2]);
                    mma16816(acc[mi][1], ah[mi], blv[1], blv[3]);
                    mma16816(acc[mi][0], al[mi], bhv[0], bhv[2]);
                    mma16816(acc[mi][1], al[mi], bhv[1], bhv[3]);
                }
            }
        }

        // epilogue: exp, rowsum, store split E
        #pragma unroll
        for (int mi = 0; mi < 4; mi++) {
            int rowA = warp_m * 64 + mi * 16 + g;
            #pragma unroll
            for (int nf = 0; nf < 2; nf++) {
                float e0 = __expf(acc[mi][nf][0]);
                float e1 = __expf(acc[mi][nf][1]);
                float e2 = __expf(acc[mi][nf][2]);
                float e3 = __expf(acc[mi][nf][3]);
                rsum[mi * 2 + 0] += e0 + e1;
                rsum[mi * 2 + 1] += e2 + e3;
                int col = c * 128 + warp_n * 16 + nf * 8 + tig * 2;
                uint32_t hp, lp;
                split2(e0, e1, hp, lp);
                *(uint32_t*)(ehb + (size_t)rowA * 2048 + col * 2) = hp;
                *(uint32_t*)(elb + (size_t)rowA * 2048 + col * 2) = lp;
                split2(e2, e3, hp, lp);
                *(uint32_t*)(ehb + (size_t)(rowA + 8) * 2048 + col * 2) = hp;
                *(uint32_t*)(elb + (size_t)(rowA + 8) * 2048 + col * 2) = lp;
            }
        }
        __syncthreads();
    }

    // rowsum reduction + inverses
    #pragma unroll
    for (int j = 0; j < 8; j++) {
        rsum[j] += __shfl_xor_sync(~0u, rsum[j], 1);
        rsum[j] += __shfl_xor_sync(~0u, rsum[j], 2);
    }
    if (tig == 0) {
        #pragma unroll
        for (int mi = 0; mi < 4; mi++) {
            int rowA = warp_m * 64 + mi * 16 + g;
            atomicAdd(&red[rowA],     rsum[mi * 2 + 0]);
            atomicAdd(&red[rowA + 8], rsum[mi * 2 + 1]);
        }
    }
    __syncthreads();
    if (tid < 128) {
        float iv = 1.0f / red[tid];
        invs[tid] = iv;
        g_inv[bh * TT + r0 + tid] = iv;
    }
    __syncthreads();

    // normalize: read E hi/lo (L2-hot), write attn_time f32
    float* at = attn_t + ((size_t)bh * TT + r0) * TT;
    #pragma unroll 4
    for (int it = 0; it < 32; it++) {
        int idx = it * 512 + tid;
        int row = idx >> 7;
        int cb = (idx & 127) * 8;
        float iv = invs[row];
        uint4 hv = *(const uint4*)(ehb + (size_t)row * 2048 + cb * 2);
        uint4 lv = *(const uint4*)(elb + (size_t)row * 2048 + cb * 2);
        float o[8];
        o[0] = join2(hv.x, lv.x, 0) * iv; o[1] = join2(hv.x, lv.x, 1) * iv;
        o[2] = join2(hv.y, lv.y, 0) * iv; o[3] = join2(hv.y, lv.y, 1) * iv;
        o[4] = join2(hv.z, lv.z, 0) * iv; o[5] = join2(hv.z, lv.z, 1) * iv;
        o[6] = join2(hv.w, lv.w, 0) * iv; o[7] = join2(hv.w, lv.w, 1) * iv;
        *(float4*)&at[(size_t)row * TT + cb]     = make_float4(o[0], o[1], o[2], o[3]);
        *(float4*)&at[(size_t)row * TT + cb + 4] = make_float4(o[4], o[5], o[6], o[7]);
    }
}

// ---------------------------------------------------------------------------
// Kernel T: tv = E @ V (16 s-chunks of 64, cp.async double-buffer), then
// out = diag(inv) * tv @ F^T.  grid (8, 64), block 512, warp tile 64x16.
// ---------------------------------------------------------------------------
#define T_A 0            // buf b at b*32768: AH +0, AL +16384
#define T_B 65536        // buf b at b*32768: BH +0, BL +16384
#define T_SMEM 131072

__global__ void __launch_bounds__(512, 1) tv_out_mma_kernel(float* __restrict__ out) {
    extern __shared__ char sm[];
    const uint32_t sb = smem_u32(sm);

    const int bh = blockIdx.y;
    const int r0 = blockIdx.x * 128;
    const int tid = threadIdx.x;
    const int wid = tid >> 5, lane = tid & 31;
    const int warp_m = wid & 1, warp_n = wid >> 1;
    const int g = lane >> 2, tig = lane & 3;
    const int rA = (lane & 7) + ((lane >> 3) & 1) * 8;
    const int xr = rA & 7, kq = lane >> 4;

    const unsigned char* ehb = g_eh + ((size_t)bh * TT + r0) * 2048;
    const unsigned char* elb = g_el + ((size_t)bh * TT + r0) * 2048;
    const unsigned char* vhb = g_vh + (size_t)bh * DD * 2048;
    const unsigned char* vlb = g_vl + (size_t)bh * DD * 2048;

    // prologue: chunk 0
    load_tile_async(sb + T_A +     0, ehb, 2048, tid);
    load_tile_async(sb + T_A + 16384, elb, 2048, tid);
    load_tile_async(sb + T_B +     0, vhb, 2048, tid);
    load_tile_async(sb + T_B + 16384, vlb, 2048, tid);
    CP_COMMIT();

    float acc[4][2][4];
    #pragma unroll
    for (int mi = 0; mi < 4; mi++)
        #pragma unroll
        for (int nf = 0; nf < 2; nf++)
            #pragma unroll
            for (int j = 0; j < 4; j++) acc[mi][nf][j] = 0.f;

    for (int c = 0; c < 16; c++) {
        if (c < 15) {
            int off = (c + 1) * 128;   // byte offset into 2048B rows
            uint32_t ab = sb + T_A + ((c + 1) & 1) * 32768;
            uint32_t bb = sb + T_B + ((c + 1) & 1) * 32768;
            load_tile_async(ab,         ehb + off, 2048, tid);
            load_tile_async(ab + 16384, elb + off, 2048, tid);
            load_tile_async(bb,         vhb + off, 2048, tid);
            load_tile_async(bb + 16384, vlb + off, 2048, tid);
            CP_COMMIT();
            CP_WAIT1();
        } else {
            CP_WAIT0();
        }
        __syncthreads();

        const uint32_t ab = sb + T_A + (c & 1) * 32768;
        const uint32_t bb = sb + T_B + (c & 1) * 32768;
        #pragma unroll
        for (int ksi = 0; ksi < 4; ksi++) {
            uint32_t ah[4][4], al[4][4], bhv[4], blv[4];
            #pragma unroll
            for (int mi = 0; mi < 4; mi++) {
                int fr = warp_m * 64 + mi * 16;
                ldsm4(a64(ab, fr, ksi, rA, xr, kq), ah[mi]);
                ldsm4(a64(ab + 16384, fr, ksi, rA, xr, kq), al[mi]);
            }
            {
                int nr = warp_n * 16;
                ldsm4(a64(bb, nr, ksi, rA, xr, kq), bhv);
                ldsm4(a64(bb + 16384, nr, ksi, rA, xr, kq), blv);
            }
            #pragma unroll
            for (int mi = 0; mi < 4; mi++) {
                mma16816(acc[mi][0], ah[mi], bhv[0], bhv[2]);
                mma16816(acc[mi][1], ah[mi], bhv[1], bhv[3]);
                mma16816(acc[mi][0], ah[mi], blv[0], blv[2]);
                mma16816(acc[mi][1], ah[mi], blv[1], blv[3]);
                mma16816(acc[mi][0], al[mi], bhv[0], bhv[2]);
                mma16816(acc[mi][1], al[mi], bhv[1], bhv[3]);
            }
        }
        __syncthreads();
    }

    // stage tv (unnormalized) split into A region: tvH kt at kt*16384, tvL at 32768+kt*16384
    {
        #pragma unroll
        for (int mi = 0; mi < 4; mi++) {
            int rowA = warp_m * 64 + mi * 16 + g;
            #pragma unroll
            for (int nf = 0; nf < 2; nf++) {
                int d0v = warp_n * 16 + nf * 8 + tig * 2;
                int kt = d0v >> 6, dc = d0v & 63;
                uint32_t hp, lp;
                split2(acc[mi][nf][0], acc[mi][nf][1], hp, lp);
                *(uint32_t*)(sm + kt * 16384 + SWZ64(rowA, dc)) = hp;
                *(uint32_t*)(sm + 32768 + kt * 16384 + SWZ64(rowA, dc)) = lp;
                split2(acc[mi][nf][2], acc[mi][nf][3], hp, lp);
                *(uint32_t*)(sm + kt * 16384 + SWZ64(rowA + 8, dc)) = hp;
                *(uint32_t*)(sm + 32768 + kt * 16384 + SWZ64(rowA + 8, dc)) = lp;
            }
        }
    }
    // F^T tiles into B region: FH kt at T_B + kt*16384, FL kt at T_B + 32768 + kt*16384
    {
        const unsigned char* fhb = g_fh + (size_t)bh * DD * 256;
        const unsigned char* flb = g_fl + (size_t)bh * DD * 256;
        load_tile_async(sb + T_B +     0, fhb,       256, tid);
        load_tile_async(sb + T_B + 16384, fhb + 128, 256, tid);
        load_tile_async(sb + T_B + 32768, flb,       256, tid);
        load_tile_async(sb + T_B + 49152, flb + 128, 256, tid);
        CP_COMMIT();
        CP_WAIT0();
    }
    __syncthreads();

    // GEMM3: out = tv @ F^T  (K = 128 = 2 kt x 4 ksi)
    float acc3[4][2][4];
    #pragma unroll
    for (int mi = 0; mi < 4; mi++)
        #pragma unroll
        for (int nf = 0; nf < 2; nf++)
            #pragma unroll
            for (int j = 0; j < 4; j++) acc3[mi][nf][j] = 0.f;

    #pragma unroll
    for (int kt = 0; kt < 2; kt++) {
        #pragma unroll
        for (int ksi = 0; ksi < 4; ksi++) {
            uint32_t ah[4][4], al[4][4], bhv[4], blv[4];
            #pragma unroll
            for (int mi = 0; mi < 4; mi++) {
                int fr = warp_m * 64 + mi * 16;
                ldsm4(a64(sb + kt * 16384, fr, ksi, rA, xr, kq), ah[mi]);
                ldsm4(a64(sb + 32768 + kt * 16384, fr, ksi, rA, xr, kq), al[mi]);
            }
            {
                int nr = warp_n * 16;
                ldsm4(a64(sb + T_B + kt * 16384, nr, ksi, rA, xr, kq), bhv);
                ldsm4(a64(sb + T_B + 32768 + kt * 16384, nr, ksi, rA, xr, kq), blv);
            }
            #pragma unroll
            for (int mi = 0; mi < 4; mi++) {
                mma16816(acc3[mi][0], ah[mi], bhv[0], bhv[2]);
                mma16816(acc3[mi][1], ah[mi], bhv[1], bhv[3]);
                mma16816(acc3[mi][0], ah[mi], blv[0], blv[2]);
                mma16816(acc3[mi][1], ah[mi], blv[1], blv[3]);
                mma16816(acc3[mi][0], al[mi], bhv[0], bhv[2]);
                mma16816(acc3[mi][1], al[mi], bhv[1], bhv[3]);
            }
        }
    }

    const float* ginv = g_inv + bh * TT + r0;
    float* op = out + ((size_t)bh * TT + r0) * DD;
    #pragma unroll
    for (int mi = 0; mi < 4; mi++) {
        int rowA = warp_m * 64 + mi * 16 + g;
        float iva = ginv[rowA];
        float ivb = ginv[rowA + 8];
        #pragma unroll
        for (int nf = 0; nf < 2; nf++) {
            int e = warp_n * 16 + nf * 8 + tig * 2;
            *(float2*)&op[(size_t)rowA * DD + e] =
                make_float2(acc3[mi][nf][0] * iva, acc3[mi][nf][1] * iva);
            *(float2*)&op[(size_t)(rowA + 8) * DD + e] =
                make_float2(acc3[mi][nf][2] * ivb, acc3[mi][nf][3] * ivb);
        }
    }
}

// ---------------------------------------------------------------------------
// Launch
// ---------------------------------------------------------------------------
extern "C" void kernel_launch(void* const* d_in, const int* in_sizes, int n_in,
                              void* d_out, int out_size) {
    const float* q_time    = (const float*)d_in[0];
    const float* k_time    = (const float*)d_in[1];
    const float* q_feature = (const float*)d_in[2];
    const float* k_feature = (const float*)d_in[3];
    const float* v         = (const float*)d_in[4];

    float* out    = (float*)d_out;                       // [BH][T][D]
    float* attn_t = out + (size_t)BHN * TT * DD;         // [BH][T][T]
    float* attn_f = attn_t + (size_t)BHN * TT * TT;      // [BH][D][D]

    cudaFuncSetAttribute(score_mma_kernel,
                         cudaFuncAttributeMaxDynamicSharedMemorySize, S_SMEM);
    cudaFuncSetAttribute(tv_out_mma_kernel,
                         cudaFuncAttributeMaxDynamicSharedMemorySize, T_SMEM);

    qk_split_kernel<<<dim3(8192, 2), 256>>>(q_time, k_time);
    v_split_T_kernel<<<dim3(32, BHN), 256>>>(v);
    feature_attn_kernel<<<dim3(4, BHN), 256>>>(q_feature, k_feature, attn_f);
    ft_split_T_kernel<<<dim3(4, BHN), 256>>>(attn_f);
    score_mma_kernel<<<dim3(8, BHN), 512, S_SMEM>>>(attn_t);
    tv_out_mma_kernel<<<dim3(8, BHN), 512, T_SMEM>>>(out);
}